// round 5
// baseline (speedup 1.0000x reference)
#include <cuda_runtime.h>
#include <cuda_bf16.h>
#include <math.h>

// ============================================================================
// ConvLSTM (2 stacked layers, 12 timesteps) on GB300.
//   Layer0: Cin=129 (1 input + 128 hidden), hid=128
//   Layer1: Cin=140 (128 from layer0 + 12 hidden), hid=12
//   B=16, H=W=64.
// Strategy: fused conv+gate kernel; packed fp32x2 FMA (fma.rn.f32x2);
// weights pre-permuted to [k][c][tap][gate] float4 for direct packed loads.
// ============================================================================

#define Bsz  16
#define Hd   64
#define Wd   64
#define HW   4096
#define LSEQ 12

#define HID0 128
#define CIN0 129   // 1 + HID0
#define HID1 12
#define CIN1 140   // HID0 + HID1

#define TILE_H 16
#define SROWS  18          // TILE_H + 2
#define SCOLS  66          // 64 + 2
#define NTILE  (SROWS*SCOLS)   // 1188

// ---------------- persistent device state (no runtime allocation) ----------
__device__ __align__(16) float g_h0[2][Bsz*HID0*HW];   // ping-pong hidden, layer0
__device__ __align__(16) float g_c0[Bsz*HID0*HW];
__device__ __align__(16) float g_h1[2][Bsz*HID1*HW];
__device__ __align__(16) float g_c1[Bsz*HID1*HW];
__device__ float4 g_wp0[HID0*CIN0*9];   // [k][c][tap] -> (wi,wf,wo,wg)
__device__ float4 g_bp0[HID0];
__device__ float4 g_wp1[HID1*CIN1*9];
__device__ float4 g_bp1[HID1];

// ---------------- packed f32x2 helpers --------------------------------------
__device__ __forceinline__ unsigned long long pack2(float a, float b) {
    unsigned long long r;
    asm("mov.b64 %0, {%1, %2};" : "=l"(r) : "f"(a), "f"(b));
    return r;
}
__device__ __forceinline__ unsigned long long fma2(unsigned long long a,
                                                   unsigned long long b,
                                                   unsigned long long c) {
    unsigned long long d;
    asm("fma.rn.f32x2 %0, %1, %2, %3;" : "=l"(d) : "l"(a), "l"(b), "l"(c));
    return d;
}
__device__ __forceinline__ void unpack2(unsigned long long v, float& lo, float& hi) {
    asm("mov.b64 {%0, %1}, %2;" : "=f"(lo), "=f"(hi) : "l"(v));
}

__device__ __forceinline__ float sigf(float x) { return 1.0f / (1.0f + expf(-x)); }

// ---------------- weight/bias permutation -----------------------------------
// W layout in: [gate*HID + k][c][kh][kw]  ->  out: [k][c][tap] float4(gates)
template<int LAYER>
__global__ void prep_w(const float* __restrict__ W, const float* __restrict__ bias) {
    constexpr int HIDN = (LAYER == 0) ? HID0 : HID1;
    constexpr int CIN  = (LAYER == 0) ? CIN0 : CIN1;
    float4* wp = (LAYER == 0) ? g_wp0 : g_wp1;
    float4* bp = (LAYER == 0) ? g_bp0 : g_bp1;

    int i = blockIdx.x * blockDim.x + threadIdx.x;
    if (i < HIDN * CIN * 9) {
        int tap = i % 9;
        int c   = (i / 9) % CIN;
        int k   = i / (9 * CIN);
        float4 v;
        v.x = W[((0 * HIDN + k) * CIN + c) * 9 + tap];   // i gate
        v.y = W[((1 * HIDN + k) * CIN + c) * 9 + tap];   // f gate
        v.z = W[((2 * HIDN + k) * CIN + c) * 9 + tap];   // o gate
        v.w = W[((3 * HIDN + k) * CIN + c) * 9 + tap];   // g gate
        wp[i] = v;
    }
    if (i < HIDN) {
        bp[i] = make_float4(bias[0 * HIDN + i], bias[1 * HIDN + i],
                            bias[2 * HIDN + i], bias[3 * HIDN + i]);
    }
}

// ---------------- state zeroing (every launch: deterministic replays) -------
__global__ void zero_state() {
    int i = blockIdx.x * blockDim.x + threadIdx.x;
    float4 z = make_float4(0.f, 0.f, 0.f, 0.f);
    if (i < (Bsz * HID0 * HW) / 4) {
        reinterpret_cast<float4*>(g_h0[0])[i] = z;
        reinterpret_cast<float4*>(g_c0)[i]    = z;
    }
    if (i < (Bsz * HID1 * HW) / 4) {
        reinterpret_cast<float4*>(g_h1[0])[i] = z;
        reinterpret_cast<float4*>(g_c1)[i]    = z;
    }
}

// ---------------- fused conv + LSTM gate step --------------------------------
// grid: (4 y-tiles, HID, B), block: 256 threads.
// Each thread: one x-column, 4 consecutive y rows, all 4 gates.
template<int LAYER>
__global__ __launch_bounds__(256, 2)
void conv_step(const float* __restrict__ history, int t, int p) {
    constexpr int HIDN = (LAYER == 0) ? HID0 : HID1;
    constexpr int CIN  = (LAYER == 0) ? CIN0 : CIN1;

    const float* srcA;           // first channel group
    const float* srcB;           // recurrent hidden channels
    const float4* __restrict__ wp;
    const float4* __restrict__ bp;
    float* cst;
    float* hout;
    if (LAYER == 0) {
        srcA = history + t * HW;         // x_t: [b][HW] with batch stride LSEQ*HW
        srcB = g_h0[p];
        wp = g_wp0; bp = g_bp0;
        cst = g_c0; hout = g_h0[p ^ 1];
    } else {
        srcA = g_h0[p ^ 1];              // layer0 output of this timestep
        srcB = g_h1[p];
        wp = g_wp1; bp = g_bp1;
        cst = g_c1; hout = g_h1[p ^ 1];
    }

    __shared__ float smem[2][NTILE];

    const int tid   = threadIdx.x;
    const int tx    = tid & 63;          // x coordinate
    const int ty4   = tid >> 6;          // 0..3 -> rows ty4*4 .. ty4*4+3
    const int ytile = blockIdx.x;
    const int k     = blockIdx.y;
    const int b     = blockIdx.z;
    const int y0    = ytile * TILE_H;

    // Precompute tile-fill indices (constant across channels)
    int  pos_[5];
    bool val_[5];
    bool st_[5];
    #pragma unroll
    for (int u = 0; u < 5; ++u) {
        int li = tid + u * 256;
        int rr = li / SCOLS;
        int cc = li - rr * SCOLS;
        int gy = y0 - 1 + rr;
        int gx = cc - 1;
        st_[u]  = (li < NTILE);
        val_[u] = st_[u] && gy >= 0 && gy < Hd && gx >= 0 && gx < Wd;
        pos_[u] = gy * Wd + gx;
    }

    // channel -> base pointer for this batch
    auto chan_ptr = [&](int c) -> const float* {
        if (LAYER == 0) {
            if (c == 0) return srcA + b * (LSEQ * HW);
            return srcB + (b * HID0 + (c - 1)) * HW;
        } else {
            if (c < HID0) return srcA + (b * HID0 + c) * HW;
            return srcB + (b * HID1 + (c - HID0)) * HW;
        }
    };

    // fill channel 0
    {
        const float* cp = chan_ptr(0);
        #pragma unroll
        for (int u = 0; u < 5; ++u) {
            if (st_[u]) smem[0][tid + u * 256] = val_[u] ? __ldg(cp + pos_[u]) : 0.f;
        }
    }
    __syncthreads();

    // accumulators: packed (i,f) and (o,g) for 4 output rows, init with bias
    unsigned long long accIF[4], accOG[4];
    {
        float4 bk = bp[k];
        unsigned long long bif = pack2(bk.x, bk.y);
        unsigned long long bog = pack2(bk.z, bk.w);
        #pragma unroll
        for (int r = 0; r < 4; ++r) { accIF[r] = bif; accOG[r] = bog; }
    }

    for (int c = 0; c < CIN; ++c) {
        // prefetch next channel tile into registers (overlaps with compute)
        float pf[5];
        if (c + 1 < CIN) {
            const float* cp = chan_ptr(c + 1);
            #pragma unroll
            for (int u = 0; u < 5; ++u)
                pf[u] = val_[u] ? __ldg(cp + pos_[u]) : 0.f;
        }

        // weights for (k, c): 9 taps, float4 = ((wi,wf),(wo,wg)) packed pairs
        const ulonglong2* wc =
            reinterpret_cast<const ulonglong2*>(wp + (k * CIN + c) * 9);
        ulonglong2 wv[9];
        #pragma unroll
        for (int u = 0; u < 9; ++u) wv[u] = wc[u];

        // compute from current smem buffer
        const float* st = smem[c & 1];
        #pragma unroll
        for (int i = 0; i < 6; ++i) {
            const float* rowp = st + (ty4 * 4 + i) * SCOLS + tx;
            float a0 = rowp[0], a1 = rowp[1], a2 = rowp[2];
            unsigned long long x0 = pack2(a0, a0);
            unsigned long long x1 = pack2(a1, a1);
            unsigned long long x2 = pack2(a2, a2);
            #pragma unroll
            for (int r = 0; r < 4; ++r) {
                const int d = i - r;       // tap row (0..2) when valid
                if (d >= 0 && d < 3) {
                    accIF[r] = fma2(wv[d * 3 + 0].x, x0, accIF[r]);
                    accOG[r] = fma2(wv[d * 3 + 0].y, x0, accOG[r]);
                    accIF[r] = fma2(wv[d * 3 + 1].x, x1, accIF[r]);
                    accOG[r] = fma2(wv[d * 3 + 1].y, x1, accOG[r]);
                    accIF[r] = fma2(wv[d * 3 + 2].x, x2, accIF[r]);
                    accOG[r] = fma2(wv[d * 3 + 2].y, x2, accOG[r]);
                }
            }
        }

        // stage next channel into the other buffer; single barrier per channel
        if (c + 1 < CIN) {
            float* sn = smem[(c + 1) & 1];
            #pragma unroll
            for (int u = 0; u < 5; ++u)
                if (st_[u]) sn[tid + u * 256] = pf[u];
        }
        __syncthreads();
    }

    // -------- LSTM gate epilogue: c' = sig(f)*c + sig(i)*tanh(g); h' = sig(o)*tanh(c')
    const int kbase = (b * HIDN + k) * HW;
    #pragma unroll
    for (int r = 0; r < 4; ++r) {
        int y   = y0 + ty4 * 4 + r;
        int idx = kbase + y * Wd + tx;
        float zi, zf, zo, zg;
        unpack2(accIF[r], zi, zf);
        unpack2(accOG[r], zo, zg);
        float cprev = cst[idx];
        float cn = sigf(zf) * cprev + sigf(zi) * tanhf(zg);
        float hn = sigf(zo) * tanhf(cn);
        cst[idx]  = cn;
        hout[idx] = hn;
    }
}

// ---------------- final output copy ------------------------------------------
// h_last of layer1 is (B,12,64,64) contiguous == (B,L,N,1) output layout.
__global__ void copy_out(float* __restrict__ out) {
    int i = blockIdx.x * blockDim.x + threadIdx.x;
    if (i < (Bsz * HID1 * HW) / 4)
        reinterpret_cast<float4*>(out)[i] =
            reinterpret_cast<const float4*>(g_h1[0])[i];
}

// ============================================================================
extern "C" void kernel_launch(void* const* d_in, const int* in_sizes, int n_in,
                              void* d_out, int out_size) {
    (void)in_sizes; (void)n_in; (void)out_size;
    const float* history = (const float*)d_in[0];   // (16,12,4096,1)
    const float* W0 = (const float*)d_in[2];        // (512,129,3,3)
    const float* b0 = (const float*)d_in[3];        // (512,)
    const float* W1 = (const float*)d_in[4];        // (48,140,3,3)
    const float* b1 = (const float*)d_in[5];        // (48,)
    float* out = (float*)d_out;

    // zero recurrent state (replay-deterministic)
    {
        int n4 = (Bsz * HID0 * HW) / 4;
        zero_state<<<(n4 + 255) / 256, 256>>>();
    }
    // weight/bias permutation
    prep_w<0><<<(HID0 * CIN0 * 9 + 255) / 256, 256>>>(W0, b0);
    prep_w<1><<<(HID1 * CIN1 * 9 + 255) / 256, 256>>>(W1, b1);

    // fused time loop: layer0 step t, then layer1 step t (consumes h0 of step t)
    for (int t = 0; t < LSEQ; ++t) {
        int p = t & 1;
        conv_step<0><<<dim3(4, HID0, Bsz), 256>>>(history, t, p);
        conv_step<1><<<dim3(4, HID1, Bsz), 256>>>(nullptr, t, p);
    }

    // after t=11, layer1 wrote h1[(11&1)^1] == h1[0]
    {
        int n4 = (Bsz * HID1 * HW) / 4;
        copy_out<<<(n4 + 255) / 256, 256>>>(out);
    }
}

// round 6
// speedup vs baseline: 1.1377x; 1.1377x over previous
#include <cuda_runtime.h>
#include <cuda_bf16.h>
#include <math.h>

// ============================================================================
// ConvLSTM (2 stacked layers, 12 timesteps) on GB300.
//   Layer0: Cin=129 (1 input + 128 hidden), hid=128
//   Layer1: Cin=140 (128 from layer0 + 12 hidden), hid=12
//   B=16, H=W=64.
// R6: KPB=2 output channels per block (2x fma per tile byte) +
//     duplicated-lane float2 smem tiles read as 64-bit packed operands
//     (kills all pack movs and in-loop address math).
// ============================================================================

#define Bsz  16
#define Hd   64
#define Wd   64
#define HW   4096
#define LSEQ 12

#define HID0 128
#define CIN0 129   // 1 + HID0
#define HID1 12
#define CIN1 140   // HID0 + HID1

#define TILE_H 16
#define SROWS  18          // TILE_H + 2
#define SCOLS  66          // 64 + 2
#define NTILE  (SROWS*SCOLS)   // 1188
#define KPB    2           // output channels per block

// ---------------- persistent device state (no runtime allocation) ----------
__device__ __align__(16) float g_h0[2][Bsz*HID0*HW];   // ping-pong hidden, layer0
__device__ __align__(16) float g_c0[Bsz*HID0*HW];
__device__ __align__(16) float g_h1[2][Bsz*HID1*HW];
__device__ __align__(16) float g_c1[Bsz*HID1*HW];
__device__ float4 g_wp0[HID0*CIN0*9];   // [k][c][tap] -> (wi,wf,wo,wg)
__device__ float4 g_bp0[HID0];
__device__ float4 g_wp1[HID1*CIN1*9];
__device__ float4 g_bp1[HID1];

// ---------------- packed f32x2 helpers --------------------------------------
__device__ __forceinline__ unsigned long long pack2(float a, float b) {
    unsigned long long r;
    asm("mov.b64 %0, {%1, %2};" : "=l"(r) : "f"(a), "f"(b));
    return r;
}
__device__ __forceinline__ unsigned long long fma2(unsigned long long a,
                                                   unsigned long long b,
                                                   unsigned long long c) {
    unsigned long long d;
    asm("fma.rn.f32x2 %0, %1, %2, %3;" : "=l"(d) : "l"(a), "l"(b), "l"(c));
    return d;
}
__device__ __forceinline__ void unpack2(unsigned long long v, float& lo, float& hi) {
    asm("mov.b64 {%0, %1}, %2;" : "=f"(lo), "=f"(hi) : "l"(v));
}

__device__ __forceinline__ float sigf(float x) { return 1.0f / (1.0f + expf(-x)); }

// ---------------- weight/bias permutation -----------------------------------
// W layout in: [gate*HID + k][c][kh][kw]  ->  out: [k][c][tap] float4(gates)
template<int LAYER>
__global__ void prep_w(const float* __restrict__ W, const float* __restrict__ bias) {
    constexpr int HIDN = (LAYER == 0) ? HID0 : HID1;
    constexpr int CIN  = (LAYER == 0) ? CIN0 : CIN1;
    float4* wp = (LAYER == 0) ? g_wp0 : g_wp1;
    float4* bp = (LAYER == 0) ? g_bp0 : g_bp1;

    int i = blockIdx.x * blockDim.x + threadIdx.x;
    if (i < HIDN * CIN * 9) {
        int tap = i % 9;
        int c   = (i / 9) % CIN;
        int k   = i / (9 * CIN);
        float4 v;
        v.x = W[((0 * HIDN + k) * CIN + c) * 9 + tap];   // i gate
        v.y = W[((1 * HIDN + k) * CIN + c) * 9 + tap];   // f gate
        v.z = W[((2 * HIDN + k) * CIN + c) * 9 + tap];   // o gate
        v.w = W[((3 * HIDN + k) * CIN + c) * 9 + tap];   // g gate
        wp[i] = v;
    }
    if (i < HIDN) {
        bp[i] = make_float4(bias[0 * HIDN + i], bias[1 * HIDN + i],
                            bias[2 * HIDN + i], bias[3 * HIDN + i]);
    }
}

// ---------------- state zeroing (every launch: deterministic replays) -------
__global__ void zero_state() {
    int i = blockIdx.x * blockDim.x + threadIdx.x;
    float4 z = make_float4(0.f, 0.f, 0.f, 0.f);
    if (i < (Bsz * HID0 * HW) / 4) {
        reinterpret_cast<float4*>(g_h0[0])[i] = z;
        reinterpret_cast<float4*>(g_c0)[i]    = z;
    }
    if (i < (Bsz * HID1 * HW) / 4) {
        reinterpret_cast<float4*>(g_h1[0])[i] = z;
        reinterpret_cast<float4*>(g_c1)[i]    = z;
    }
}

// ---------------- fused conv + LSTM gate step --------------------------------
// grid: (4 y-tiles, HIDN/KPB, B), block: 256 threads.
// Each thread: one x-column, 4 consecutive y rows, KPB output channels, 4 gates.
// Activation tiles live in smem as duplicated-lane float2 (v,v), so a single
// 64-bit LDS yields a ready f32x2 operand for fma.rn.f32x2 (no pack movs).
template<int LAYER>
__global__ __launch_bounds__(256, 2)
void conv_step(const float* __restrict__ history, int t, int p) {
    constexpr int HIDN = (LAYER == 0) ? HID0 : HID1;
    constexpr int CIN  = (LAYER == 0) ? CIN0 : CIN1;

    const float* srcA;           // first channel group
    const float* srcB;           // recurrent hidden channels
    const float4* __restrict__ wp;
    const float4* __restrict__ bp;
    float* cst;
    float* hout;
    if (LAYER == 0) {
        srcA = history + t * HW;         // x_t: [b][HW] with batch stride LSEQ*HW
        srcB = g_h0[p];
        wp = g_wp0; bp = g_bp0;
        cst = g_c0; hout = g_h0[p ^ 1];
    } else {
        srcA = g_h0[p ^ 1];              // layer0 output of this timestep
        srcB = g_h1[p];
        wp = g_wp1; bp = g_bp1;
        cst = g_c1; hout = g_h1[p ^ 1];
    }

    __shared__ float2 smem[2][NTILE];    // duplicated lanes: .x == .y

    const int tid   = threadIdx.x;
    const int tx    = tid & 63;          // x coordinate
    const int ty4   = tid >> 6;          // 0..3 -> rows ty4*4 .. ty4*4+3
    const int ytile = blockIdx.x;
    const int k0    = blockIdx.y * KPB;
    const int b     = blockIdx.z;
    const int y0    = ytile * TILE_H;

    // Precompute tile-fill indices (constant across channels)
    int  pos_[5];
    bool val_[5];
    bool st_[5];
    #pragma unroll
    for (int u = 0; u < 5; ++u) {
        int li = tid + u * 256;
        int rr = li / SCOLS;
        int cc = li - rr * SCOLS;
        int gy = y0 - 1 + rr;
        int gx = cc - 1;
        st_[u]  = (li < NTILE);
        val_[u] = st_[u] && gy >= 0 && gy < Hd && gx >= 0 && gx < Wd;
        pos_[u] = gy * Wd + gx;
    }

    // channel -> base pointer for this batch
    auto chan_ptr = [&](int c) -> const float* {
        if (LAYER == 0) {
            if (c == 0) return srcA + b * (LSEQ * HW);
            return srcB + (b * HID0 + (c - 1)) * HW;
        } else {
            if (c < HID0) return srcA + (b * HID0 + c) * HW;
            return srcB + (b * HID1 + (c - HID0)) * HW;
        }
    };

    // fill channel 0
    {
        const float* cp = chan_ptr(0);
        #pragma unroll
        for (int u = 0; u < 5; ++u) {
            if (st_[u]) {
                float v = val_[u] ? __ldg(cp + pos_[u]) : 0.f;
                smem[0][tid + u * 256] = make_float2(v, v);
            }
        }
    }
    __syncthreads();

    // accumulators: packed (i,f) and (o,g) for 4 rows x KPB channels, init bias
    unsigned long long accIF[KPB][4], accOG[KPB][4];
    #pragma unroll
    for (int kk = 0; kk < KPB; ++kk) {
        float4 bk = bp[k0 + kk];
        unsigned long long bif = pack2(bk.x, bk.y);
        unsigned long long bog = pack2(bk.z, bk.w);
        #pragma unroll
        for (int r = 0; r < 4; ++r) { accIF[kk][r] = bif; accOG[kk][r] = bog; }
    }

    const int base0 = (ty4 * 4) * SCOLS + tx;

    for (int c = 0; c < CIN; ++c) {
        // prefetch next channel tile into registers (overlaps with compute)
        float pf[5];
        if (c + 1 < CIN) {
            const float* cp = chan_ptr(c + 1);
            #pragma unroll
            for (int u = 0; u < 5; ++u)
                pf[u] = val_[u] ? __ldg(cp + pos_[u]) : 0.f;
        }

        // weights for (k0..k0+KPB-1, c): 9 taps each, ((wi,wf),(wo,wg)) pairs
        ulonglong2 wv[KPB][9];
        #pragma unroll
        for (int kk = 0; kk < KPB; ++kk) {
            const ulonglong2* wc =
                reinterpret_cast<const ulonglong2*>(wp + ((k0 + kk) * CIN + c) * 9);
            #pragma unroll
            for (int u = 0; u < 9; ++u) wv[kk][u] = wc[u];
        }

        // compute from current smem buffer (64-bit packed operand loads)
        const unsigned long long* st =
            reinterpret_cast<const unsigned long long*>(smem[c & 1]);
        #pragma unroll
        for (int i = 0; i < 6; ++i) {
            unsigned long long x0 = st[base0 + i * SCOLS + 0];
            unsigned long long x1 = st[base0 + i * SCOLS + 1];
            unsigned long long x2 = st[base0 + i * SCOLS + 2];
            #pragma unroll
            for (int kk = 0; kk < KPB; ++kk) {
                #pragma unroll
                for (int r = 0; r < 4; ++r) {
                    const int d = i - r;       // tap row (0..2) when valid
                    if (d >= 0 && d < 3) {
                        accIF[kk][r] = fma2(wv[kk][d * 3 + 0].x, x0, accIF[kk][r]);
                        accOG[kk][r] = fma2(wv[kk][d * 3 + 0].y, x0, accOG[kk][r]);
                        accIF[kk][r] = fma2(wv[kk][d * 3 + 1].x, x1, accIF[kk][r]);
                        accOG[kk][r] = fma2(wv[kk][d * 3 + 1].y, x1, accOG[kk][r]);
                        accIF[kk][r] = fma2(wv[kk][d * 3 + 2].x, x2, accIF[kk][r]);
                        accOG[kk][r] = fma2(wv[kk][d * 3 + 2].y, x2, accOG[kk][r]);
                    }
                }
            }
        }

        // stage next channel into the other buffer; single barrier per channel
        if (c + 1 < CIN) {
            float2* sn = smem[(c + 1) & 1];
            #pragma unroll
            for (int u = 0; u < 5; ++u)
                if (st_[u]) sn[tid + u * 256] = make_float2(pf[u], pf[u]);
        }
        __syncthreads();
    }

    // -------- LSTM gate epilogue: c' = sig(f)*c + sig(i)*tanh(g); h' = sig(o)*tanh(c')
    #pragma unroll
    for (int kk = 0; kk < KPB; ++kk) {
        const int kbase = (b * HIDN + (k0 + kk)) * HW;
        #pragma unroll
        for (int r = 0; r < 4; ++r) {
            int y   = y0 + ty4 * 4 + r;
            int idx = kbase + y * Wd + tx;
            float zi, zf, zo, zg;
            unpack2(accIF[kk][r], zi, zf);
            unpack2(accOG[kk][r], zo, zg);
            float cprev = cst[idx];
            float cn = sigf(zf) * cprev + sigf(zi) * tanhf(zg);
            float hn = sigf(zo) * tanhf(cn);
            cst[idx]  = cn;
            hout[idx] = hn;
        }
    }
}

// ---------------- final output copy ------------------------------------------
// h_last of layer1 is (B,12,64,64) contiguous == (B,L,N,1) output layout.
__global__ void copy_out(float* __restrict__ out) {
    int i = blockIdx.x * blockDim.x + threadIdx.x;
    if (i < (Bsz * HID1 * HW) / 4)
        reinterpret_cast<float4*>(out)[i] =
            reinterpret_cast<const float4*>(g_h1[0])[i];
}

// ============================================================================
extern "C" void kernel_launch(void* const* d_in, const int* in_sizes, int n_in,
                              void* d_out, int out_size) {
    (void)in_sizes; (void)n_in; (void)out_size;
    const float* history = (const float*)d_in[0];   // (16,12,4096,1)
    const float* W0 = (const float*)d_in[2];        // (512,129,3,3)
    const float* b0 = (const float*)d_in[3];        // (512,)
    const float* W1 = (const float*)d_in[4];        // (48,140,3,3)
    const float* b1 = (const float*)d_in[5];        // (48,)
    float* out = (float*)d_out;

    // zero recurrent state (replay-deterministic)
    {
        int n4 = (Bsz * HID0 * HW) / 4;
        zero_state<<<(n4 + 255) / 256, 256>>>();
    }
    // weight/bias permutation
    prep_w<0><<<(HID0 * CIN0 * 9 + 255) / 256, 256>>>(W0, b0);
    prep_w<1><<<(HID1 * CIN1 * 9 + 255) / 256, 256>>>(W1, b1);

    // fused time loop: layer0 step t, then layer1 step t (consumes h0 of step t)
    for (int t = 0; t < LSEQ; ++t) {
        int p = t & 1;
        conv_step<0><<<dim3(4, HID0 / KPB, Bsz), 256>>>(history, t, p);
        conv_step<1><<<dim3(4, HID1 / KPB, Bsz), 256>>>(nullptr, t, p);
    }

    // after t=11, layer1 wrote h1[(11&1)^1] == h1[0]
    {
        int n4 = (Bsz * HID1 * HW) / 4;
        copy_out<<<(n4 + 255) / 256, 256>>>(out);
    }
}

// round 7
// speedup vs baseline: 1.3699x; 1.2041x over previous
#include <cuda_runtime.h>
#include <cuda_bf16.h>
#include <math.h>

// ============================================================================
// ConvLSTM (2 stacked layers, 12 timesteps) on GB300.
//   Layer0: Cin=129 (1 input + 128 hidden), hid=128
//   Layer1: Cin=140 (128 from layer0 + 12 hidden), hid=12
//   B=16, H=W=64.
// R7: tied-operand fma.rn.f32x2 (kills 1 MOV-pair per FMA), KPB=4 output
//     channels per block, tap-row-sliced weight loads (12 transient regs)
//     to stay under the 128-reg / 2-CTA ceiling.
// ============================================================================

#define Bsz  16
#define Hd   64
#define Wd   64
#define HW   4096
#define LSEQ 12

#define HID0 128
#define CIN0 129   // 1 + HID0
#define HID1 12
#define CIN1 140   // HID0 + HID1

#define TILE_H 16
#define SROWS  18          // TILE_H + 2
#define SCOLS  66          // 64 + 2
#define NTILE  (SROWS*SCOLS)   // 1188
#define KPB    4           // output channels per block

typedef unsigned long long u64t;

// ---------------- persistent device state (no runtime allocation) ----------
__device__ __align__(16) float g_h0[2][Bsz*HID0*HW];   // ping-pong hidden, layer0
__device__ __align__(16) float g_c0[Bsz*HID0*HW];
__device__ __align__(16) float g_h1[2][Bsz*HID1*HW];
__device__ __align__(16) float g_c1[Bsz*HID1*HW];
__device__ float4 g_wp0[HID0*CIN0*9];   // [k][c][tap] -> (wi,wf,wo,wg)
__device__ float4 g_bp0[HID0];
__device__ float4 g_wp1[HID1*CIN1*9];
__device__ float4 g_bp1[HID1];

// ---------------- packed f32x2 helpers --------------------------------------
__device__ __forceinline__ u64t pack2(float a, float b) {
    u64t r;
    asm("mov.b64 %0, {%1, %2};" : "=l"(r) : "f"(a), "f"(b));
    return r;
}
// In-place accumulate: tied "+l" constraint -> no destination copy.
__device__ __forceinline__ void fma2ip(u64t& acc, u64t a, u64t b) {
    asm("fma.rn.f32x2 %0, %1, %2, %0;" : "+l"(acc) : "l"(a), "l"(b));
}
__device__ __forceinline__ void unpack2(u64t v, float& lo, float& hi) {
    asm("mov.b64 {%0, %1}, %2;" : "=f"(lo), "=f"(hi) : "l"(v));
}

__device__ __forceinline__ float sigf(float x) { return 1.0f / (1.0f + expf(-x)); }

// ---------------- weight/bias permutation -----------------------------------
// W layout in: [gate*HID + k][c][kh][kw]  ->  out: [k][c][tap] float4(gates)
template<int LAYER>
__global__ void prep_w(const float* __restrict__ W, const float* __restrict__ bias) {
    constexpr int HIDN = (LAYER == 0) ? HID0 : HID1;
    constexpr int CIN  = (LAYER == 0) ? CIN0 : CIN1;
    float4* wp = (LAYER == 0) ? g_wp0 : g_wp1;
    float4* bp = (LAYER == 0) ? g_bp0 : g_bp1;

    int i = blockIdx.x * blockDim.x + threadIdx.x;
    if (i < HIDN * CIN * 9) {
        int tap = i % 9;
        int c   = (i / 9) % CIN;
        int k   = i / (9 * CIN);
        float4 v;
        v.x = W[((0 * HIDN + k) * CIN + c) * 9 + tap];   // i gate
        v.y = W[((1 * HIDN + k) * CIN + c) * 9 + tap];   // f gate
        v.z = W[((2 * HIDN + k) * CIN + c) * 9 + tap];   // o gate
        v.w = W[((3 * HIDN + k) * CIN + c) * 9 + tap];   // g gate
        wp[i] = v;
    }
    if (i < HIDN) {
        bp[i] = make_float4(bias[0 * HIDN + i], bias[1 * HIDN + i],
                            bias[2 * HIDN + i], bias[3 * HIDN + i]);
    }
}

// ---------------- state zeroing (every launch: deterministic replays) -------
__global__ void zero_state() {
    int i = blockIdx.x * blockDim.x + threadIdx.x;
    float4 z = make_float4(0.f, 0.f, 0.f, 0.f);
    if (i < (Bsz * HID0 * HW) / 4) {
        reinterpret_cast<float4*>(g_h0[0])[i] = z;
        reinterpret_cast<float4*>(g_c0)[i]    = z;
    }
    if (i < (Bsz * HID1 * HW) / 4) {
        reinterpret_cast<float4*>(g_h1[0])[i] = z;
        reinterpret_cast<float4*>(g_c1)[i]    = z;
    }
}

// ---------------- fused conv + LSTM gate step --------------------------------
// grid: (4 y-tiles, HIDN/KPB, B), block: 256 threads.
// Each thread: one x-column, 4 consecutive y rows, KPB=4 output channels.
// Activation tiles: duplicated-lane float2 in smem -> one LDS.64 = packed op.
// Weights: JIT per (kk, tap-row) from L1 (uniform broadcast), only 12
// transient regs live, keeping total under 128 for 2 CTAs/SM.
template<int LAYER>
__global__ __launch_bounds__(256, 2)
void conv_step(const float* __restrict__ history, int t, int p) {
    constexpr int HIDN = (LAYER == 0) ? HID0 : HID1;
    constexpr int CIN  = (LAYER == 0) ? CIN0 : CIN1;

    const float* srcA;           // first channel group
    const float* srcB;           // recurrent hidden channels
    const float4* __restrict__ wp;
    const float4* __restrict__ bp;
    float* cst;
    float* hout;
    if (LAYER == 0) {
        srcA = history + t * HW;         // x_t: [b][HW] with batch stride LSEQ*HW
        srcB = g_h0[p];
        wp = g_wp0; bp = g_bp0;
        cst = g_c0; hout = g_h0[p ^ 1];
    } else {
        srcA = g_h0[p ^ 1];              // layer0 output of this timestep
        srcB = g_h1[p];
        wp = g_wp1; bp = g_bp1;
        cst = g_c1; hout = g_h1[p ^ 1];
    }

    __shared__ float2 smem[2][NTILE];    // duplicated lanes: .x == .y

    const int tid   = threadIdx.x;
    const int tx    = tid & 63;          // x coordinate
    const int ty4   = tid >> 6;          // 0..3 -> rows ty4*4 .. ty4*4+3
    const int ytile = blockIdx.x;
    const int k0    = blockIdx.y * KPB;
    const int b     = blockIdx.z;
    const int y0    = ytile * TILE_H;

    // Precompute tile-fill indices (constant across channels)
    int  pos_[5];
    bool val_[5];
    bool st_[5];
    #pragma unroll
    for (int u = 0; u < 5; ++u) {
        int li = tid + u * 256;
        int rr = li / SCOLS;
        int cc = li - rr * SCOLS;
        int gy = y0 - 1 + rr;
        int gx = cc - 1;
        st_[u]  = (li < NTILE);
        val_[u] = st_[u] && gy >= 0 && gy < Hd && gx >= 0 && gx < Wd;
        pos_[u] = gy * Wd + gx;
    }

    // channel -> base pointer for this batch
    auto chan_ptr = [&](int c) -> const float* {
        if (LAYER == 0) {
            if (c == 0) return srcA + b * (LSEQ * HW);
            return srcB + (b * HID0 + (c - 1)) * HW;
        } else {
            if (c < HID0) return srcA + (b * HID0 + c) * HW;
            return srcB + (b * HID1 + (c - HID0)) * HW;
        }
    };

    // fill channel 0
    {
        const float* cp = chan_ptr(0);
        #pragma unroll
        for (int u = 0; u < 5; ++u) {
            if (st_[u]) {
                float v = val_[u] ? __ldg(cp + pos_[u]) : 0.f;
                smem[0][tid + u * 256] = make_float2(v, v);
            }
        }
    }
    __syncthreads();

    // accumulators: packed (i,f) and (o,g) for 4 rows x KPB channels, init bias
    u64t accIF[KPB][4], accOG[KPB][4];
    #pragma unroll
    for (int kk = 0; kk < KPB; ++kk) {
        float4 bk = bp[k0 + kk];
        u64t bif = pack2(bk.x, bk.y);
        u64t bog = pack2(bk.z, bk.w);
        #pragma unroll
        for (int r = 0; r < 4; ++r) { accIF[kk][r] = bif; accOG[kk][r] = bog; }
    }

    const int base0 = (ty4 * 4) * SCOLS + tx;
    // running weight pointer for channel c: wp + (k0*CIN + c)*9
    const ulonglong2* wrun =
        reinterpret_cast<const ulonglong2*>(wp + (k0 * CIN) * 9);

    for (int c = 0; c < CIN; ++c) {
        // fill next channel's buffer (other half) -- overlaps with compute,
        // no long-lived prefetch registers
        if (c + 1 < CIN) {
            const float* cp = chan_ptr(c + 1);
            float2* sn = smem[(c + 1) & 1];
            #pragma unroll
            for (int u = 0; u < 5; ++u) {
                if (st_[u]) {
                    float v = val_[u] ? __ldg(cp + pos_[u]) : 0.f;
                    sn[tid + u * 256] = make_float2(v, v);
                }
            }
        }

        // load all 18 activation operands for this channel (packed f32x2)
        u64t ax[6][3];
        {
            const u64t* st = reinterpret_cast<const u64t*>(smem[c & 1]);
            #pragma unroll
            for (int i = 0; i < 6; ++i)
                #pragma unroll
                for (int j = 0; j < 3; ++j)
                    ax[i][j] = st[base0 + i * SCOLS + j];
        }

        // KPB output channels; per (kk, tap-row d): load 3 taps (6 u64, 12
        // transient regs), then 4 output rows x 3 cols x 2 packs = 24 fma2
        #pragma unroll
        for (int kk = 0; kk < KPB; ++kk) {
            const ulonglong2* wc = wrun + kk * (CIN * 9);
            #pragma unroll
            for (int d = 0; d < 3; ++d) {
                ulonglong2 w0 = wc[d * 3 + 0];
                ulonglong2 w1 = wc[d * 3 + 1];
                ulonglong2 w2 = wc[d * 3 + 2];
                #pragma unroll
                for (int r = 0; r < 4; ++r) {
                    const int i = d + r;           // smem row index
                    fma2ip(accIF[kk][r], w0.x, ax[i][0]);
                    fma2ip(accOG[kk][r], w0.y, ax[i][0]);
                    fma2ip(accIF[kk][r], w1.x, ax[i][1]);
                    fma2ip(accOG[kk][r], w1.y, ax[i][1]);
                    fma2ip(accIF[kk][r], w2.x, ax[i][2]);
                    fma2ip(accOG[kk][r], w2.y, ax[i][2]);
                }
            }
        }
        wrun += 9;

        __syncthreads();
    }

    // -------- LSTM gate epilogue: c' = sig(f)*c + sig(i)*tanh(g); h' = sig(o)*tanh(c')
    #pragma unroll
    for (int kk = 0; kk < KPB; ++kk) {
        const int kbase = (b * HIDN + (k0 + kk)) * HW;
        #pragma unroll
        for (int r = 0; r < 4; ++r) {
            int y   = y0 + ty4 * 4 + r;
            int idx = kbase + y * Wd + tx;
            float zi, zf, zo, zg;
            unpack2(accIF[kk][r], zi, zf);
            unpack2(accOG[kk][r], zo, zg);
            float cprev = cst[idx];
            float cn = sigf(zf) * cprev + sigf(zi) * tanhf(zg);
            float hn = sigf(zo) * tanhf(cn);
            cst[idx]  = cn;
            hout[idx] = hn;
        }
    }
}

// ---------------- final output copy ------------------------------------------
// h_last of layer1 is (B,12,64,64) contiguous == (B,L,N,1) output layout.
__global__ void copy_out(float* __restrict__ out) {
    int i = blockIdx.x * blockDim.x + threadIdx.x;
    if (i < (Bsz * HID1 * HW) / 4)
        reinterpret_cast<float4*>(out)[i] =
            reinterpret_cast<const float4*>(g_h1[0])[i];
}

// ============================================================================
extern "C" void kernel_launch(void* const* d_in, const int* in_sizes, int n_in,
                              void* d_out, int out_size) {
    (void)in_sizes; (void)n_in; (void)out_size;
    const float* history = (const float*)d_in[0];   // (16,12,4096,1)
    const float* W0 = (const float*)d_in[2];        // (512,129,3,3)
    const float* b0 = (const float*)d_in[3];        // (512,)
    const float* W1 = (const float*)d_in[4];        // (48,140,3,3)
    const float* b1 = (const float*)d_in[5];        // (48,)
    float* out = (float*)d_out;

    // zero recurrent state (replay-deterministic)
    {
        int n4 = (Bsz * HID0 * HW) / 4;
        zero_state<<<(n4 + 255) / 256, 256>>>();
    }
    // weight/bias permutation
    prep_w<0><<<(HID0 * CIN0 * 9 + 255) / 256, 256>>>(W0, b0);
    prep_w<1><<<(HID1 * CIN1 * 9 + 255) / 256, 256>>>(W1, b1);

    // fused time loop: layer0 step t, then layer1 step t (consumes h0 of step t)
    for (int t = 0; t < LSEQ; ++t) {
        int p = t & 1;
        conv_step<0><<<dim3(4, HID0 / KPB, Bsz), 256>>>(history, t, p);
        conv_step<1><<<dim3(4, HID1 / KPB, Bsz), 256>>>(nullptr, t, p);
    }

    // after t=11, layer1 wrote h1[(11&1)^1] == h1[0]
    {
        int n4 = (Bsz * HID1 * HW) / 4;
        copy_out<<<(n4 + 255) / 256, 256>>>(out);
    }
}